// round 13
// baseline (speedup 1.0000x reference)
#include <cuda_runtime.h>
#include <cuda_fp16.h>
#include <math.h>
#include <stdint.h>

// Problem constants: B=4, T=2048, D=1024, H=16, HD=64
#define BB    4
#define TT    2048
#define DD    1024
#define HH    16
#define BT    (BB*TT)          // 8192

#define LOG2E 1.44269504088896340736f

// ---------------------------------------------------------------------------
// helpers (plain sm_80+ PTX only)
// ---------------------------------------------------------------------------
__device__ __forceinline__ uint32_t smem_u32(const void* p) {
    uint32_t a;
    asm("{ .reg .u64 t; cvta.to.shared.u64 t, %1; cvt.u32.u64 %0, t; }"
        : "=r"(a) : "l"(p));
    return a;
}
__device__ __forceinline__ void cpa(uint32_t s, const void* g) {
    asm volatile("cp.async.cg.shared.global [%0], [%1], 16;" :: "r"(s), "l"(g));
}
#define CPA_COMMIT() asm volatile("cp.async.commit_group;" ::: "memory")
#define CPA_WAIT(n)  asm volatile("cp.async.wait_group %0;" :: "n"(n) : "memory")

__device__ __forceinline__ float ex2(float x) {   // single-MUFU exp2
    float r;
    asm("ex2.approx.ftz.f32 %0, %1;" : "=f"(r) : "f"(x));
    return r;
}

__device__ __forceinline__ void ldsm_x4(uint32_t a, uint32_t& r0, uint32_t& r1,
                                        uint32_t& r2, uint32_t& r3) {
    asm volatile("ldmatrix.sync.aligned.m8n8.x4.shared.b16 {%0,%1,%2,%3}, [%4];"
                 : "=r"(r0), "=r"(r1), "=r"(r2), "=r"(r3) : "r"(a));
}
__device__ __forceinline__ void ldsm_x4t(uint32_t a, uint32_t& r0, uint32_t& r1,
                                         uint32_t& r2, uint32_t& r3) {
    asm volatile("ldmatrix.sync.aligned.m8n8.x4.trans.shared.b16 {%0,%1,%2,%3}, [%4];"
                 : "=r"(r0), "=r"(r1), "=r"(r2), "=r"(r3) : "r"(a));
}
__device__ __forceinline__ void mma_f16(float* c, uint32_t a0, uint32_t a1,
                                        uint32_t a2, uint32_t a3,
                                        uint32_t b0, uint32_t b1) {
    asm volatile(
        "mma.sync.aligned.m16n8k16.row.col.f32.f16.f16.f32 "
        "{%0,%1,%2,%3}, {%4,%5,%6,%7}, {%8,%9}, {%0,%1,%2,%3};"
        : "+f"(c[0]), "+f"(c[1]), "+f"(c[2]), "+f"(c[3])
        : "r"(a0), "r"(a1), "r"(a2), "r"(a3), "r"(b0), "r"(b1));
}
__device__ __forceinline__ uint32_t pkh(float x, float y) {
    __half2 t = __floats2half2_rn(x, y);
    return *(uint32_t*)&t;
}
#define SWZ128(x) ((x) ^ (((x) >> 3) & 0x70))

// ---------------------------------------------------------------------------
// scratch (__device__ globals; no allocation allowed)
// ---------------------------------------------------------------------------
__device__ __half g_xh[(size_t)BT * DD];         // x fp16
__device__ __half g_wq[(size_t)3 * DD * DD];     // qkv_w fp16
__device__ __half g_wo[(size_t)DD * DD];         // out_w fp16
__device__ __half g_oh[(size_t)BT * DD];         // attn out fp16
__device__ __half g_qh[(size_t)64 * TT * 64];    // [bh][t][hd] (scaled)
__device__ __half g_kh[(size_t)64 * TT * 64];
__device__ __half g_vh[(size_t)64 * TT * 64];
__device__ float g_bias[BT];      // log2 domain: mask ? -1e9 : log2(clip(eng))
__device__ int   g_maskType;

// ---------------------------------------------------------------------------
__global__ void detect_kernel(const unsigned* __restrict__ mw)
{
    int tid = threadIdx.x;
    int isI = 1, isF = 1, isB = 1;
    for (int i = tid; i < 2048; i += 256) {
        unsigned w = mw[i];
        if (w > 1u) isI = 0;
        if (w != 0u && w != 0x3F800000u) isF = 0;
        if (w != 0u && w != 0x00003F80u && w != 0x3F800000u && w != 0x3F803F80u) isB = 0;
    }
    isI = __syncthreads_and(isI);
    isF = __syncthreads_and(isF);
    isB = __syncthreads_and(isB);
    if (tid == 0) g_maskType = isI ? 0 : (isF ? 1 : (isB ? 3 : 2));
}

__global__ void bias_kernel(const float* __restrict__ eng, const void* __restrict__ mask)
{
    int i = blockIdx.x * 256 + threadIdx.x;
    if (i >= BT) return;
    int ty = g_maskType;
    bool m;
    if (ty == 0)      m = ((const int*)mask)[i] != 0;
    else if (ty == 1) m = ((const float*)mask)[i] != 0.0f;
    else if (ty == 3) m = ((const unsigned short*)mask)[i] != 0;
    else              m = ((const unsigned char*)mask)[i] != 0;
    g_bias[i] = m ? -1e9f : log2f(fmaxf(eng[i], 1e-6f));
}

// merged fp32 -> fp16 conversion for x | qkv_w | out_w  (8 elems / thread)
#define CVT_N1 (BT * DD)          // 8388608
#define CVT_N2 (3 * DD * DD)      // 3145728
#define CVT_N3 (DD * DD)          // 1048576
__global__ void cvt_all(const float* __restrict__ x,
                        const float* __restrict__ wq,
                        const float* __restrict__ wo)
{
    size_t i = ((size_t)blockIdx.x * 256 + threadIdx.x) * 8;
    const float* src; __half* dst; size_t off;
    if (i < CVT_N1)               { src = x;  dst = g_xh; off = i; }
    else if (i < CVT_N1 + CVT_N2) { src = wq; dst = g_wq; off = i - CVT_N1; }
    else if (i < CVT_N1 + CVT_N2 + CVT_N3)
                                  { src = wo; dst = g_wo; off = i - CVT_N1 - CVT_N2; }
    else return;
    float4 a = *(const float4*)(src + off);
    float4 b = *(const float4*)(src + off + 4);
    __align__(16) __half h[8];
    h[0] = __float2half_rn(a.x); h[1] = __float2half_rn(a.y);
    h[2] = __float2half_rn(a.z); h[3] = __float2half_rn(a.w);
    h[4] = __float2half_rn(b.x); h[5] = __float2half_rn(b.y);
    h[6] = __float2half_rn(b.z); h[7] = __float2half_rn(b.w);
    *(uint4*)(dst + off) = *(uint4*)h;
}

// ---------------------------------------------------------------------------
// HMMA fp16 NT GEMM: C[M,N] = A·B^T (+bias), K=1024.
// block 128x128, BK=64, 8 warps (2x4), warp tile 64x32, cp.async 3-stage,
// single barrier per iteration (copy issued after the barrier).
// mode 0: A=g_xh, B=g_wq -> q (scaled) / k / v head planes
// mode 1: A=g_oh, B=g_wo -> C fp32 row-major [*,1024]
// ---------------------------------------------------------------------------
#define GSTG   32768   // per-stage smem: A 16KB + B 16KB
#define NCHUNK 16      // 1024 / 64
#define GSM    (3 * GSTG)

__device__ __forceinline__ void gemm_copy(uint32_t sb, int st, int kt,
                                          const __half* A, const __half* Bm,
                                          int m0, int n0, int tid)
{
    int kb = kt * 64;
    for (int i = tid; i < 2048; i += 256) {
        int half_ = i >> 10, idx = i & 1023;
        int row = idx >> 3, cc = idx & 7;
        const __half* src = half_
            ? Bm + (size_t)(n0 + row) * DD + kb + cc * 8
            : A  + (size_t)(m0 + row) * DD + kb + cc * 8;
        cpa(sb + st * GSTG + half_ * 16384 + SWZ128((uint32_t)(row * 128 + cc * 16)), src);
    }
    CPA_COMMIT();
}

__global__ __launch_bounds__(256, 2)
void gemm_hmma(const float* __restrict__ bias, float* __restrict__ C, int mode)
{
    extern __shared__ char smem[];
    const uint32_t sb = smem_u32(smem);
    const int tid = threadIdx.x, lane = tid & 31, wid = tid >> 5;
    const int m0 = blockIdx.y * 128, n0 = blockIdx.x * 128;
    const int wm = wid & 1, wn = wid >> 1;

    const __half* A  = (mode == 0) ? g_xh : g_oh;
    const __half* Bm = (mode == 0) ? g_wq : g_wo;

    float c[4][4][4];
#pragma unroll
    for (int a = 0; a < 4; a++)
#pragma unroll
        for (int b = 0; b < 4; b++)
#pragma unroll
            for (int e = 0; e < 4; e++) c[a][b][e] = 0.0f;

    gemm_copy(sb, 0, 0, A, Bm, m0, n0, tid);
    gemm_copy(sb, 1, 1, A, Bm, m0, n0, tid);

    for (int kt = 0; kt < NCHUNK; kt++) {
        if (kt + 1 < NCHUNK) CPA_WAIT(1);
        else                 CPA_WAIT(0);
        __syncthreads();
        if (kt + 2 < NCHUNK)
            gemm_copy(sb, (kt + 2) % 3, kt + 2, A, Bm, m0, n0, tid);

        const uint32_t Ab = sb + (kt % 3) * GSTG, Bb = Ab + 16384;
#pragma unroll
        for (int kc = 0; kc < 4; kc++) {
            uint32_t a[4][4];
#pragma unroll
            for (int mt = 0; mt < 4; mt++) {
                int row = wm * 64 + mt * 16 + (lane & 15);
                ldsm_x4(Ab + SWZ128((uint32_t)(row * 128 + kc * 32 + ((lane >> 4) << 4))),
                        a[mt][0], a[mt][1], a[mt][2], a[mt][3]);
            }
            uint32_t bf[4][2];
#pragma unroll
            for (int np = 0; np < 2; np++) {
                int lg = lane >> 3;
                int rowb = wn * 32 + np * 16 + ((lg & 2) ? 8 : 0) + (lane & 7);
                ldsm_x4(Bb + SWZ128((uint32_t)(rowb * 128 + kc * 32 + ((lg & 1) << 4))),
                        bf[2 * np][0], bf[2 * np][1], bf[2 * np + 1][0], bf[2 * np + 1][1]);
            }
#pragma unroll
            for (int mt = 0; mt < 4; mt++)
#pragma unroll
                for (int nb = 0; nb < 4; nb++)
                    mma_f16(c[mt][nb], a[mt][0], a[mt][1], a[mt][2], a[mt][3],
                            bf[nb][0], bf[nb][1]);
        }
    }

    const float QS = 0.125f * LOG2E;
#pragma unroll
    for (int mt = 0; mt < 4; mt++) {
        int r0 = m0 + wm * 64 + mt * 16 + (lane >> 2);
#pragma unroll
        for (int nb = 0; nb < 4; nb++) {
            int col = n0 + wn * 32 + nb * 8 + (lane & 3) * 2;
            float b0 = bias[col], b1 = bias[col + 1];
#pragma unroll
            for (int hh = 0; hh < 2; hh++) {
                int row = r0 + hh * 8;
                float v0 = c[mt][nb][2 * hh]     + b0;
                float v1 = c[mt][nb][2 * hh + 1] + b1;
                if (mode == 0) {
                    int which = col >> 10, d = col & 1023, h = d >> 6, hd = d & 63;
                    int bb = row >> 11, t = row & 2047;
                    size_t idx = ((size_t)(bb * 16 + h) * TT + t) * 64 + hd;
                    if (which == 0) {
                        v0 *= QS; v1 *= QS;
                        *(uint32_t*)&g_qh[idx] = pkh(v0, v1);
                    } else if (which == 1) {
                        *(uint32_t*)&g_kh[idx] = pkh(v0, v1);
                    } else {
                        *(uint32_t*)&g_vh[idx] = pkh(v0, v1);
                    }
                } else {
                    float2 vv; vv.x = v0; vv.y = v1;
                    *(float2*)&C[(size_t)row * DD + col] = vv;
                }
            }
        }
    }
}

// ---------------------------------------------------------------------------
// HMMA fp16 flash attention, fixed-max softmax, Q fragments hoisted,
// 3-stage K/V cp.async pipeline, single barrier per iteration.
// block = 128 queries x one (b,h). 256 thr, 8 warps.
// smem: Q 16KB | K 3x8KB | V 3x8KB | bias 3x256B = 66304 B
// ---------------------------------------------------------------------------
#define AT_K   16384u
#define AT_V   40960u
#define AT_BI  65536u
#define AT_SM  66304

__device__ __forceinline__ void attn_copyKV(uint32_t sb, int buf, int bh, int b,
                                            int k0, int tid)
{
    for (int i = tid; i < 1024; i += 256) {
        int sel = i >> 9, idx = i & 511;           // 0=K, 1=V
        int row = idx >> 3, cc = idx & 7;
        size_t go = ((size_t)bh * TT + k0 + row) * 64 + cc * 8;
        const __half* src = sel ? g_vh + go : g_kh + go;
        uint32_t dst = sb + (sel ? AT_V : AT_K) + buf * 8192 +
                       SWZ128((uint32_t)(row * 128 + cc * 16));
        cpa(dst, src);
    }
    if (tid < 16) cpa(sb + AT_BI + buf * 256 + tid * 16, g_bias + (size_t)b * TT + k0 + tid * 4);
    CPA_COMMIT();
}

__global__ __launch_bounds__(256, 2)
void attn_hmma()
{
    extern __shared__ char smem[];
    const uint32_t sb = smem_u32(smem);
    const int tid = threadIdx.x, lane = tid & 31, w = tid >> 5;
    const int bh = blockIdx.y, b = bh >> 4, h = bh & 15;
    const int q0 = blockIdx.x << 7;   // 128 queries per block

    attn_copyKV(sb, 0, bh, b, 0, tid);
    attn_copyKV(sb, 1, bh, b, 64, tid);

    // Q tile -> smem -> hoisted register fragments (loop-invariant)
    for (int i = tid; i < 1024; i += 256) {
        int row = i >> 3, cc = i & 7;
        const __half* src = g_qh + ((size_t)bh * TT + q0 + row) * 64 + cc * 8;
        *(uint4*)(smem + SWZ128((uint32_t)(row * 128 + cc * 16))) = *(const uint4*)src;
    }
    __syncthreads();
    uint32_t qf[4][4];
#pragma unroll
    for (int kc = 0; kc < 4; kc++) {
        int row = w * 16 + (lane & 15);
        ldsm_x4(sb + SWZ128((uint32_t)(row * 128 + kc * 32 + ((lane >> 4) << 4))),
                qf[kc][0], qf[kc][1], qf[kc][2], qf[kc][3]);
    }

    float o[8][4];
#pragma unroll
    for (int nb = 0; nb < 8; nb++)
#pragma unroll
        for (int e = 0; e < 4; e++) o[nb][e] = 0.0f;
    float l0part = 0.0f, l1part = 0.0f;   // per-thread row-sum partials

    for (int kt = 0; kt < 32; kt++) {
        const int buf = kt % 3;
        if (kt + 1 < 32) CPA_WAIT(1);
        else             CPA_WAIT(0);
        __syncthreads();
        if (kt + 2 < 32)
            attn_copyKV(sb, (kt + 2) % 3, bh, b, (kt + 2) * 64, tid);

        // ---- S = Q·K^T over HD=64 (Q fragments already in regs)
        float s[8][4];
#pragma unroll
        for (int nb = 0; nb < 8; nb++)
#pragma unroll
            for (int e = 0; e < 4; e++) s[nb][e] = 0.0f;

        const uint32_t kb = sb + AT_K + buf * 8192;
#pragma unroll
        for (int kc = 0; kc < 4; kc++) {
#pragma unroll
            for (int np = 0; np < 4; np++) {
                int lg = lane >> 3;
                int rowb = np * 16 + ((lg & 2) ? 8 : 0) + (lane & 7);
                uint32_t b0, b1, b2, b3;
                ldsm_x4(kb + SWZ128((uint32_t)(rowb * 128 + kc * 32 + ((lg & 1) << 4))),
                        b0, b1, b2, b3);
                mma_f16(s[2 * np],     qf[kc][0], qf[kc][1], qf[kc][2], qf[kc][3], b0, b1);
                mma_f16(s[2 * np + 1], qf[kc][0], qf[kc][1], qf[kc][2], qf[kc][3], b2, b3);
            }
        }

        // ---- p = 2^(s + bias); accumulate per-thread row sums
        const float* biasS = (const float*)(smem + AT_BI + buf * 256);
#pragma unroll
        for (int nb = 0; nb < 8; nb++) {
            int col = nb * 8 + (lane & 3) * 2;
            float b0 = biasS[col], b1 = biasS[col + 1];
            float p0 = ex2(s[nb][0] + b0);
            float p1 = ex2(s[nb][1] + b1);
            float p2 = ex2(s[nb][2] + b0);
            float p3 = ex2(s[nb][3] + b1);
            s[nb][0] = p0; s[nb][1] = p1; s[nb][2] = p2; s[nb][3] = p3;
            l0part += p0 + p1;
            l1part += p2 + p3;
        }

        // ---- O += P·V
        const uint32_t vb = sb + AT_V + buf * 8192;
#pragma unroll
        for (int kc2 = 0; kc2 < 4; kc2++) {
            const float* pa = s[2 * kc2];
            const float* pb = s[2 * kc2 + 1];
            uint32_t ph0 = pkh(pa[0], pa[1]), ph1 = pkh(pa[2], pa[3]);
            uint32_t ph2 = pkh(pb[0], pb[1]), ph3 = pkh(pb[2], pb[3]);
            int lg = lane >> 3;
            int rowv = kc2 * 16 + ((lg & 1) ? 8 : 0) + (lane & 7);
#pragma unroll
            for (int np = 0; np < 4; np++) {
                uint32_t off = SWZ128((uint32_t)(rowv * 128 + np * 32 + ((lg & 2) ? 16 : 0)));
                uint32_t v0, v1, v2, v3;
                ldsm_x4t(vb + off, v0, v1, v2, v3);
                mma_f16(o[2 * np],     ph0, ph1, ph2, ph3, v0, v1);
                mma_f16(o[2 * np + 1], ph0, ph1, ph2, ph3, v2, v3);
            }
        }
    }

    // ---- single final row-sum reduction across the quad, then normalize
    l0part += __shfl_xor_sync(0xffffffffu, l0part, 1);
    l0part += __shfl_xor_sync(0xffffffffu, l0part, 2);
    l1part += __shfl_xor_sync(0xffffffffu, l1part, 1);
    l1part += __shfl_xor_sync(0xffffffffu, l1part, 2);
    float inv0 = 1.0f / l0part, inv1 = 1.0f / l1part;

    size_t gt0 = (size_t)b * TT + q0 + w * 16 + (lane >> 2);
    size_t gt1 = gt0 + 8;
#pragma unroll
    for (int nb = 0; nb < 8; nb++) {
        int col = h * 64 + nb * 8 + (lane & 3) * 2;
        *(uint32_t*)&g_oh[gt0 * DD + col] = pkh(o[nb][0] * inv0, o[nb][1] * inv0);
        *(uint32_t*)&g_oh[gt1 * DD + col] = pkh(o[nb][2] * inv1, o[nb][3] * inv1);
    }
}

// ---------------------------------------------------------------------------
extern "C" void kernel_launch(void* const* d_in, const int* in_sizes, int n_in,
                              void* d_out, int out_size)
{
    const float* x    = (const float*)d_in[0];
    const float* eng  = (const float*)d_in[1];
    const void*  mask = d_in[2];
    const float* qkvw = (const float*)d_in[3];
    const float* qkvb = (const float*)d_in[4];
    const float* outw = (const float*)d_in[5];
    const float* outb = (const float*)d_in[6];
    float* out = (float*)d_out;

    static int attrDone = 0;
    if (!attrDone) {
        cudaFuncSetAttribute(gemm_hmma, cudaFuncAttributeMaxDynamicSharedMemorySize, GSM);
        cudaFuncSetAttribute(attn_hmma, cudaFuncAttributeMaxDynamicSharedMemorySize, AT_SM);
        attrDone = 1;
    }

    detect_kernel<<<1, 256>>>((const unsigned*)mask);
    bias_kernel<<<(BT + 255) / 256, 256>>>(eng, mask);

    // merged conversions: x | qkv_w | out_w
    cvt_all<<<((CVT_N1 + CVT_N2 + CVT_N3) / 8 + 255) / 256, 256>>>(x, qkvw, outw);

    // QKV projection: [8192 x 3072]
    gemm_hmma<<<dim3(24, 64), 256, GSM>>>(qkvb, nullptr, 0);

    // attention: 16 q-blocks x 64 (b,h)
    attn_hmma<<<dim3(16, 64), 256, AT_SM>>>();

    // output projection: [8192 x 1024]
    gemm_hmma<<<dim3(8, 64), 256, GSM>>>(outb, out, 1);
}